// round 6
// baseline (speedup 1.0000x reference)
#include <cuda_runtime.h>
#include <math.h>

#define BATCH 16384
#define KDIM 128
#define CLS 32
#define PL 132             // sS pitch
#define PW 68              // 64-block pitch
#define P3 36              // 32-block pitch
#define RCHUNK 16
#define RPC (BATCH / RCHUNK)   // 1024
#define MSZ (KDIM * KDIM)      // 16384

// ---------------- scratch (device globals: allocation-free) ----------------
__device__ float g_sum[CLS * KDIM];
__device__ int   g_cnt[CLS];
__device__ int   g_first[CLS];
__device__ float g_Gp[RCHUNK * CLS * MSZ];  // partial Grams (32 MB)
__device__ float g_S[CLS * MSZ];
__device__ float g_inv[CLS * MSZ];
__device__ float g_mu[CLS * KDIM];
__device__ float g_ld2[CLS];

// ---------------- K0: zero small scratch + output ----------------
__global__ void k_init(float* out) {
    int i = blockIdx.x * blockDim.x + threadIdx.x;
    if (i < CLS * KDIM) g_sum[i] = 0.0f;
    if (i < CLS) { g_cnt[i] = 0; g_first[i] = BATCH; }
    if (i == 0) out[0] = 0.0f;
}

// ------- K1: per-(chunk,class) partial Gram + fused sums/count/first -------
__global__ __launch_bounds__(256) void k_scatter(const float* __restrict__ feat,
                                                 const int* __restrict__ lab) {
    const int c = blockIdx.y;
    const int chunk = blockIdx.x;
    const int R0 = chunk * RPC;
    __shared__ int s_idx[RPC];
    __shared__ int s_n, s_min;
    __shared__ __align__(16) float s_x[16][KDIM];
    const int tid = threadIdx.x;
    if (tid == 0) { s_n = 0; s_min = BATCH; }
    __syncthreads();

    for (int r = R0 + tid; r < R0 + RPC; r += 256) {
        if (lab[r] == c) {
            int p = atomicAdd(&s_n, 1);
            s_idx[p] = r;
            atomicMin(&s_min, r);
        }
    }
    __syncthreads();
    const int n = s_n;

    float acc[8][8];
#pragma unroll
    for (int u = 0; u < 8; u++)
#pragma unroll
        for (int v = 0; v < 8; v++) acc[u][v] = 0.0f;
    float csum = 0.0f;

    const int ty = tid >> 4, tx = tid & 15;

    for (int t = 0; t < n; t += 16) {
        int m = min(16, n - t);
        for (int i = tid; i < m * 32; i += 256) {
            int rr = i >> 5, q = i & 31;
            ((float4*)s_x[rr])[q] =
                ((const float4*)(feat + (size_t)s_idx[t + rr] * KDIM))[q];
        }
        __syncthreads();
        if (tid < KDIM)
            for (int e = 0; e < m; e++) csum += s_x[e][tid];
        for (int e = 0; e < m; e++) {
            float a[8], b[8];
#pragma unroll
            for (int u = 0; u < 8; u++) { a[u] = s_x[e][ty * 8 + u]; b[u] = s_x[e][tx * 8 + u]; }
#pragma unroll
            for (int u = 0; u < 8; u++)
#pragma unroll
                for (int v = 0; v < 8; v++) acc[u][v] = fmaf(a[u], b[v], acc[u][v]);
        }
        __syncthreads();
    }

    // plain (non-atomic) store of the partial Gram — even zeros when n == 0
    float* G = g_Gp + ((size_t)chunk * CLS + c) * MSZ;
#pragma unroll
    for (int u = 0; u < 8; u++) {
        float4 lo = make_float4(acc[u][0], acc[u][1], acc[u][2], acc[u][3]);
        float4 hi = make_float4(acc[u][4], acc[u][5], acc[u][6], acc[u][7]);
        *(float4*)&G[(ty * 8 + u) * KDIM + tx * 8]     = lo;
        *(float4*)&G[(ty * 8 + u) * KDIM + tx * 8 + 4] = hi;
    }

    if (n > 0) {
        if (tid < KDIM) atomicAdd(&g_sum[c * KDIM + tid], csum);
        if (tid == 0) { atomicAdd(&g_cnt[c], n); atomicMin(&g_first[c], s_min); }
    }
}

// ---------------- warp Gauss-Jordan inverse of SPD 32x32 (in-place) --------
__device__ __forceinline__ void gj32(float* M, int P, float* ldacc) {
    const int lane = threadIdx.x & 31;
    float y[32];
#pragma unroll
    for (int m = 0; m < 32; m++) y[m] = M[lane * P + m];
    float ld = 0.0f;
#pragma unroll
    for (int j = 0; j < 32; j++) {
        float pj = __shfl_sync(0xffffffffu, y[j], j);
        float r = __fdividef(1.0f, pj);
        float c = y[j];
        if (lane == j) {
            ld = log2f(pj);
#pragma unroll
            for (int m = 0; m < 32; m++) y[m] *= r;
            y[j] = r;
        }
#pragma unroll
        for (int m = 0; m < 32; m++) {
            float rowj = __shfl_sync(0xffffffffu, y[m], j);
            if (lane != j && m != j) y[m] -= c * rowj;
        }
        if (lane != j) y[j] = -c * r;
    }
#pragma unroll
    for (int m = 0; m < 32; m++) M[lane * P + m] = y[m];
#pragma unroll
    for (int o = 16; o; o >>= 1) ld += __shfl_xor_sync(0xffffffffu, ld, o);
    if (lane == 0) *ldacc += ld;
}

// ------- 64-GEMM: O = c0s*C0 + sgn*op(P)·Q ; 512 threads, 2x4 tiles --------
template<bool TRA>
__device__ __forceinline__ void sgemm64(const float* __restrict__ P, int pp,
                                        const float* __restrict__ Q, int pq,
                                        float* __restrict__ O, int po,
                                        const float* __restrict__ C0, int pc,
                                        float c0s, float sgn) {
    const int r0 = (threadIdx.x >> 4) * 2;
    const int c0 = (threadIdx.x & 15) << 2;
    float x0[4] = {0,0,0,0}, x1[4] = {0,0,0,0};
#pragma unroll 8
    for (int m = 0; m < 64; m++) {
        float4 b = *(const float4*)&Q[m * pq + c0];
        float a0 = TRA ? P[m * pp + r0]     : P[r0 * pp + m];
        float a1 = TRA ? P[m * pp + r0 + 1] : P[(r0 + 1) * pp + m];
        x0[0] = fmaf(a0, b.x, x0[0]); x0[1] = fmaf(a0, b.y, x0[1]);
        x0[2] = fmaf(a0, b.z, x0[2]); x0[3] = fmaf(a0, b.w, x0[3]);
        x1[0] = fmaf(a1, b.x, x1[0]); x1[1] = fmaf(a1, b.y, x1[1]);
        x1[2] = fmaf(a1, b.z, x1[2]); x1[3] = fmaf(a1, b.w, x1[3]);
    }
    float4 o0 = make_float4(sgn*x0[0], sgn*x0[1], sgn*x0[2], sgn*x0[3]);
    float4 o1 = make_float4(sgn*x1[0], sgn*x1[1], sgn*x1[2], sgn*x1[3]);
    if (C0) {
        float4 ca = *(const float4*)&C0[r0 * pc + c0];
        float4 cb = *(const float4*)&C0[(r0 + 1) * pc + c0];
        o0.x += c0s*ca.x; o0.y += c0s*ca.y; o0.z += c0s*ca.z; o0.w += c0s*ca.w;
        o1.x += c0s*cb.x; o1.y += c0s*cb.y; o1.z += c0s*cb.z; o1.w += c0s*cb.w;
    }
    *(float4*)&O[r0 * po + c0]       = o0;
    *(float4*)&O[(r0 + 1) * po + c0] = o1;
}

// ------- 32-GEMM: 256 active threads, 1x4 tiles ------------------------
template<bool TRA>
__device__ __forceinline__ void sgemm32(const float* __restrict__ P, int pp,
                                        const float* __restrict__ Q, int pq,
                                        float* __restrict__ O, int po,
                                        const float* __restrict__ C0, int pc,
                                        float c0s, float sgn) {
    if (threadIdx.x >= 256) return;
    const int r0 = threadIdx.x >> 3;
    const int c0 = (threadIdx.x & 7) << 2;
    float x[4] = {0,0,0,0};
#pragma unroll
    for (int m = 0; m < 32; m++) {
        float4 b = *(const float4*)&Q[m * pq + c0];
        float a = TRA ? P[m * pp + r0] : P[r0 * pp + m];
        x[0] = fmaf(a, b.x, x[0]); x[1] = fmaf(a, b.y, x[1]);
        x[2] = fmaf(a, b.z, x[2]); x[3] = fmaf(a, b.w, x[3]);
    }
    float4 o = make_float4(sgn*x[0], sgn*x[1], sgn*x[2], sgn*x[3]);
    if (C0) {
        float4 cc = *(const float4*)&C0[r0 * pc + c0];
        o.x += c0s*cc.x; o.y += c0s*cc.y; o.z += c0s*cc.z; o.w += c0s*cc.w;
    }
    *(float4*)&O[r0 * po + c0] = o;
}

// ---------------- 64x64 SPD inverse via one-level Schur (in place) ---------
__device__ void inv64(float* M, int pm, float* ldacc,
                      float* w, float* t, float* u) {
    if (threadIdx.x < 32) gj32(M, pm, ldacc);               // a -> inva
    __syncthreads();
    sgemm32<false>(M + 32 * pm, pm, M, pm, w, P3, (const float*)0, 0, 0.f, 1.f);
    __syncthreads();
    sgemm32<false>(w, P3, M + 32, pm, t, P3, M + 32 * pm + 32, pm, 1.f, -1.f);
    __syncthreads();
    if (threadIdx.x < 32) gj32(t, P3, ldacc);               // t -> invt
    __syncthreads();
    sgemm32<false>(t, P3, w, P3, u, P3, (const float*)0, 0, 0.f, 1.f);
    __syncthreads();
    sgemm32<true>(w, P3, u, P3, M, pm, M, pm, 1.f, 1.f);
    for (int idx = threadIdx.x; idx < 1024; idx += blockDim.x) {
        int i = idx >> 5, j = idx & 31;
        M[(32 + i) * pm + 32 + j] = t[i * P3 + j];
        M[(32 + i) * pm + j]      = -u[i * P3 + j];
        M[i * pm + 32 + j]        = -u[j * P3 + i];
    }
    __syncthreads();
}

// ---------------- K2: per-class S, S^{-1} (Schur D&C), log2det -------------
__global__ __launch_bounds__(512, 1) void k_sinv() {
    extern __shared__ float sm[];
    float* sS  = sm;                       // 128 * PL
    float* sW  = sS + KDIM * PL;           // 64 * PW
    float* sT  = sW + 64 * PW;
    float* sU  = sT + 64 * PW;
    float* s3a = sU + 64 * PW;             // 32 * P3 x3
    float* s3b = s3a + 32 * P3;
    float* s3c = s3b + 32 * P3;
    __shared__ float s_mu[KDIM];
    __shared__ float s_ld;

    const int c = blockIdx.x, tid = threadIdx.x;

    float rn = 1.0f / (float)g_cnt[c];
    if (tid < KDIM) {
        float m = g_sum[c * KDIM + tid] * rn;
        s_mu[tid] = m;
        g_mu[c * KDIM + tid] = m;
    }
    if (tid == 0) s_ld = 0.0f;
    __syncthreads();

    // build S = (sum_p Gp)/n - mu mu^T + I   (into smem + g_S)
    float* Sg = g_S + (size_t)c * MSZ;
    for (int idx = tid; idx < MSZ / 4; idx += 512) {
        int a = idx >> 5, b4 = (idx & 31) << 2;
        float4 s = make_float4(0.f, 0.f, 0.f, 0.f);
        const float* gp = g_Gp + (size_t)c * MSZ + a * KDIM + b4;
#pragma unroll
        for (int p = 0; p < RCHUNK; p++) {
            float4 t = *(const float4*)(gp + (size_t)p * CLS * MSZ);
            s.x += t.x; s.y += t.y; s.z += t.z; s.w += t.w;
        }
        float ma = s_mu[a];
        s.x = s.x * rn - ma * s_mu[b4 + 0] + (b4 + 0 == a ? 1.0f : 0.0f);
        s.y = s.y * rn - ma * s_mu[b4 + 1] + (b4 + 1 == a ? 1.0f : 0.0f);
        s.z = s.z * rn - ma * s_mu[b4 + 2] + (b4 + 2 == a ? 1.0f : 0.0f);
        s.w = s.w * rn - ma * s_mu[b4 + 3] + (b4 + 3 == a ? 1.0f : 0.0f);
        *(float4*)&sS[a * PL + b4] = s;
        *(float4*)&Sg[a * KDIM + b4] = s;
    }
    __syncthreads();

    // ---- S = [[A, Bt],[B, C]] ; two-level Schur inverse ----
    inv64(sS, PL, &s_ld, s3a, s3b, s3c);                     // A -> invA
    sgemm64<false>(sS + 64 * PL, PL, sS, PL, sW, PW, (const float*)0, 0, 0.f, 1.f); // W = B·invA
    __syncthreads();
    sgemm64<false>(sW, PW, sS + 64, PL, sT, PW, sS + 64 * PL + 64, PL, 1.f, -1.f);  // T = C - W·B^T
    __syncthreads();
    inv64(sT, PW, &s_ld, s3a, s3b, s3c);                     // T -> invT
    sgemm64<false>(sT, PW, sW, PW, sU, PW, (const float*)0, 0, 0.f, 1.f);           // U = invT·W
    __syncthreads();
    sgemm64<true>(sW, PW, sU, PW, sS, PL, sS, PL, 1.f, 1.f); // TL = invA + W^T·U
    for (int idx = tid; idx < 64 * 64; idx += 512) {
        int i = idx >> 6, j = idx & 63;
        sS[(64 + i) * PL + 64 + j] = sT[i * PW + j];
        sS[(64 + i) * PL + j]      = -sU[i * PW + j];
        sS[i * PL + 64 + j]        = -sU[j * PW + i];
    }
    __syncthreads();

    // dump inverse + logdet
    float* Ig = g_inv + (size_t)c * MSZ;
    for (int idx = tid; idx < MSZ / 4; idx += 512) {
        int a = idx >> 5, b4 = (idx & 31) << 2;
        *(float4*)&Ig[a * KDIM + b4] = *(const float4*)&sS[a * PL + b4];
    }
    if (tid == 0) g_ld2[c] = s_ld;
}

// ---------------- K3: pairwise KL + mask + final reduction -----------------
__global__ void k_final(float* out) {
    int i = blockIdx.x >> 5, j = blockIdx.x & 31;
    int tid = threadIdx.x;
    __shared__ float sv[KDIM];
    __shared__ float2 sred[256];
    __shared__ int smask;

    if (tid == 0) {
        int fi = g_first[i], fj = g_first[j], ri = 0, rj = 0;
        for (int c = 0; c < CLS; c++) { int f = g_first[c]; ri += (f < fi); rj += (f < fj); }
        smask = (ri <= CLS - 2) && (rj >= 1);
    }
    if (tid < KDIM) sv[tid] = g_mu[i * KDIM + tid] - g_mu[j * KDIM + tid];
    __syncthreads();

    float tr = 0.0f, qd = 0.0f;
    if (smask) {
        const float* Sp = g_S + (size_t)i * MSZ;
        const float* Ip = g_inv + (size_t)j * MSZ;
        for (int idx = tid; idx < MSZ; idx += 256) {
            float w = Ip[idx];
            tr += w * Sp[idx];
            qd += w * sv[idx >> 7] * sv[idx & 127];
        }
    }
    sred[tid] = make_float2(tr, qd);
    __syncthreads();
    for (int s = 128; s; s >>= 1) {
        if (tid < s) { sred[tid].x += sred[tid + s].x; sred[tid].y += sred[tid + s].y; }
        __syncthreads();
    }
    if (tid == 0 && smask) {
        float kl = 0.5f * ((g_ld2[j] - g_ld2[i]) - (float)KDIM + sred[0].y + sred[0].x);
        atomicAdd(out, kl);
    }

    if (blockIdx.x == 0) {
        __syncthreads();
        float m2 = 0.0f;
        for (int idx = tid; idx < CLS * KDIM; idx += 256) { float m = g_mu[idx]; m2 += m * m; }
        sred[tid].x = m2;
        __syncthreads();
        for (int s = 128; s; s >>= 1) { if (tid < s) sred[tid].x += sred[tid + s].x; __syncthreads(); }
        if (tid == 0) atomicAdd(out, -sred[0].x);
    }
}

// ---------------- launch ----------------
extern "C" void kernel_launch(void* const* d_in, const int* in_sizes, int n_in,
                              void* d_out, int out_size) {
    const float* feat = (const float*)d_in[0];
    const int*   lab  = (const int*)d_in[1];
    float* out = (float*)d_out;

    const int SINV_SMEM = (KDIM * PL + 3 * 64 * PW + 3 * 32 * P3) * (int)sizeof(float);
    cudaFuncSetAttribute(k_sinv, cudaFuncAttributeMaxDynamicSharedMemorySize, SINV_SMEM);

    k_init<<<16, 256>>>(out);
    k_scatter<<<dim3(RCHUNK, CLS), 256>>>(feat, lab);
    k_sinv<<<CLS, 512, SINV_SMEM>>>();
    k_final<<<CLS * CLS, 256>>>(out);
}

// round 7
// speedup vs baseline: 1.1694x; 1.1694x over previous
#include <cuda_runtime.h>
#include <math.h>

#define BATCH 16384
#define KDIM 128
#define CLS 32
#define PL 132             // sS pitch (%4==0)
#define PW 68              // 64-block pitch (%4==0)
#define P3 36              // 32-block pitch (%4==0)
#define RCHUNK 8
#define RPC (BATCH / RCHUNK)   // 2048
#define MSZ (KDIM * KDIM)      // 16384

// ---------------- scratch (device globals: allocation-free) ----------------
__device__ float g_sum[CLS * KDIM];
__device__ int   g_cnt[CLS];
__device__ int   g_first[CLS];
__device__ float g_G[CLS * MSZ];
__device__ float g_S[CLS * MSZ];
__device__ float g_inv[CLS * MSZ];
__device__ float g_mu[CLS * KDIM];
__device__ float g_ld2[CLS];

// ---------------- K0: zero scratch + output ----------------
__global__ void k_init(float* out) {
    int i = blockIdx.x * blockDim.x + threadIdx.x;
    if (i < CLS * MSZ) g_G[i] = 0.0f;
    if (i < CLS * KDIM) g_sum[i] = 0.0f;
    if (i < CLS) { g_cnt[i] = 0; g_first[i] = BATCH; }
    if (i == 0) out[0] = 0.0f;
}

// ------- K1: per-class Gram (atomic) + fused sums/count/first --------------
__global__ __launch_bounds__(256) void k_scatter(const float* __restrict__ feat,
                                                 const int* __restrict__ lab) {
    const int c = blockIdx.y;
    const int chunk = blockIdx.x;
    const int R0 = chunk * RPC;
    __shared__ int s_idx[RPC];
    __shared__ int s_n, s_min;
    __shared__ __align__(16) float s_x[16][KDIM];
    const int tid = threadIdx.x;
    if (tid == 0) { s_n = 0; s_min = BATCH; }
    __syncthreads();

    for (int r = R0 + tid; r < R0 + RPC; r += 256) {
        if (lab[r] == c) {
            int p = atomicAdd(&s_n, 1);
            s_idx[p] = r;
            atomicMin(&s_min, r);
        }
    }
    __syncthreads();
    const int n = s_n;
    if (n == 0) return;

    float acc[8][8];
#pragma unroll
    for (int u = 0; u < 8; u++)
#pragma unroll
        for (int v = 0; v < 8; v++) acc[u][v] = 0.0f;
    float csum = 0.0f;

    const int ty = tid >> 4, tx = tid & 15;

    for (int t = 0; t < n; t += 16) {
        int m = min(16, n - t);
        for (int i = tid; i < m * 32; i += 256) {
            int rr = i >> 5, q = i & 31;
            ((float4*)s_x[rr])[q] =
                ((const float4*)(feat + (size_t)s_idx[t + rr] * KDIM))[q];
        }
        __syncthreads();
        if (tid < KDIM)
            for (int e = 0; e < m; e++) csum += s_x[e][tid];
        for (int e = 0; e < m; e++) {
            float a[8], b[8];
#pragma unroll
            for (int u = 0; u < 8; u++) { a[u] = s_x[e][ty * 8 + u]; b[u] = s_x[e][tx * 8 + u]; }
#pragma unroll
            for (int u = 0; u < 8; u++)
#pragma unroll
                for (int v = 0; v < 8; v++) acc[u][v] = fmaf(a[u], b[v], acc[u][v]);
        }
        __syncthreads();
    }

    float* G = g_G + (size_t)c * MSZ;
#pragma unroll
    for (int u = 0; u < 8; u++)
#pragma unroll
        for (int v = 0; v < 8; v++)
            atomicAdd(&G[(ty * 8 + u) * KDIM + (tx * 8 + v)], acc[u][v]);

    if (tid < KDIM) atomicAdd(&g_sum[c * KDIM + tid], csum);
    if (tid == 0) { atomicAdd(&g_cnt[c], n); atomicMin(&g_first[c], s_min); }
}

// ---------------- warp Gauss-Jordan inverse of SPD 32x32 (in-place) --------
__device__ __forceinline__ void gj32(float* M, int P, float* ldacc) {
    const int lane = threadIdx.x & 31;
    float y[32];
#pragma unroll
    for (int m = 0; m < 32; m++) y[m] = M[lane * P + m];
    float ld = 0.0f;
#pragma unroll
    for (int j = 0; j < 32; j++) {
        float pj = __shfl_sync(0xffffffffu, y[j], j);
        float r = __fdividef(1.0f, pj);
        float c = y[j];
        if (lane == j) {
            ld = log2f(pj);
#pragma unroll
            for (int m = 0; m < 32; m++) y[m] *= r;
            y[j] = r;
        }
#pragma unroll
        for (int m = 0; m < 32; m++) {
            float rowj = __shfl_sync(0xffffffffu, y[m], j);
            if (lane != j && m != j) y[m] -= c * rowj;
        }
        if (lane != j) y[j] = -c * r;
    }
#pragma unroll
    for (int m = 0; m < 32; m++) M[lane * P + m] = y[m];
#pragma unroll
    for (int o = 16; o; o >>= 1) ld += __shfl_xor_sync(0xffffffffu, ld, o);
    if (lane == 0) *ldacc += ld;
}

// ------ 64-GEMM (256 thr, 4x4 tiles): O = c0s*C0 + sgn*op(P)·Q -------------
// A-side scalar (warp-broadcast friendly); B/C0/O side float4.
template<bool TRA>
__device__ __forceinline__ void sgemm64(const float* __restrict__ P, int pp,
                                        const float* __restrict__ Q, int pq,
                                        float* __restrict__ O, int po,
                                        const float* __restrict__ C0, int pc,
                                        float c0s, float sgn) {
    const int r0 = (threadIdx.x >> 4) * 4;
    const int c0 = (threadIdx.x & 15) * 4;
    float acc[4][4];
#pragma unroll
    for (int u = 0; u < 4; u++)
#pragma unroll
        for (int v = 0; v < 4; v++) acc[u][v] = 0.0f;
#pragma unroll 4
    for (int m = 0; m < 64; m++) {
        float4 b = *(const float4*)&Q[m * pq + c0];
        float a[4];
        if (TRA) {
            float4 t = *(const float4*)&P[m * pp + r0];
            a[0] = t.x; a[1] = t.y; a[2] = t.z; a[3] = t.w;
        } else {
#pragma unroll
            for (int u = 0; u < 4; u++) a[u] = P[(r0 + u) * pp + m];
        }
#pragma unroll
        for (int u = 0; u < 4; u++) {
            acc[u][0] = fmaf(a[u], b.x, acc[u][0]);
            acc[u][1] = fmaf(a[u], b.y, acc[u][1]);
            acc[u][2] = fmaf(a[u], b.z, acc[u][2]);
            acc[u][3] = fmaf(a[u], b.w, acc[u][3]);
        }
    }
#pragma unroll
    for (int u = 0; u < 4; u++) {
        float4 o = make_float4(sgn * acc[u][0], sgn * acc[u][1],
                               sgn * acc[u][2], sgn * acc[u][3]);
        if (C0) {
            float4 cc = *(const float4*)&C0[(r0 + u) * pc + c0];
            o.x += c0s * cc.x; o.y += c0s * cc.y;
            o.z += c0s * cc.z; o.w += c0s * cc.w;
        }
        *(float4*)&O[(r0 + u) * po + c0] = o;
    }
}

// ------ 32-GEMM (256 thr, 2x2 tiles) ----------------------------------------
template<bool TRA>
__device__ __forceinline__ void sgemm32(const float* __restrict__ P, int pp,
                                        const float* __restrict__ Q, int pq,
                                        float* __restrict__ O, int po,
                                        const float* __restrict__ C0, int pc,
                                        float c0s, float sgn) {
    const int r0 = (threadIdx.x >> 4) * 2;
    const int c0 = (threadIdx.x & 15) * 2;
    float acc[2][2] = {{0.f, 0.f}, {0.f, 0.f}};
#pragma unroll 8
    for (int m = 0; m < 32; m++) {
        float2 b = *(const float2*)&Q[m * pq + c0];
        float a0 = TRA ? P[m * pp + r0]     : P[r0 * pp + m];
        float a1 = TRA ? P[m * pp + r0 + 1] : P[(r0 + 1) * pp + m];
        acc[0][0] = fmaf(a0, b.x, acc[0][0]); acc[0][1] = fmaf(a0, b.y, acc[0][1]);
        acc[1][0] = fmaf(a1, b.x, acc[1][0]); acc[1][1] = fmaf(a1, b.y, acc[1][1]);
    }
#pragma unroll
    for (int u = 0; u < 2; u++) {
        float2 o = make_float2(sgn * acc[u][0], sgn * acc[u][1]);
        if (C0) {
            float2 cc = *(const float2*)&C0[(r0 + u) * pc + c0];
            o.x += c0s * cc.x; o.y += c0s * cc.y;
        }
        *(float2*)&O[(r0 + u) * po + c0] = o;
    }
}

// ---------------- 64x64 SPD inverse via one-level Schur (in place) ---------
__device__ void inv64(float* M, int pm, float* ldacc,
                      float* w, float* t, float* u) {
    if (threadIdx.x < 32) gj32(M, pm, ldacc);               // a -> inva
    __syncthreads();
    sgemm32<false>(M + 32 * pm, pm, M, pm, w, P3, (const float*)0, 0, 0.f, 1.f);
    __syncthreads();
    sgemm32<false>(w, P3, M + 32, pm, t, P3, M + 32 * pm + 32, pm, 1.f, -1.f);
    __syncthreads();
    if (threadIdx.x < 32) gj32(t, P3, ldacc);               // t -> invt
    __syncthreads();
    sgemm32<false>(t, P3, w, P3, u, P3, (const float*)0, 0, 0.f, 1.f);
    __syncthreads();
    sgemm32<true>(w, P3, u, P3, M, pm, M, pm, 1.f, 1.f);    // TL = inva + w^T u
    for (int idx = threadIdx.x; idx < 1024; idx += 256) {
        int i = idx >> 5, j = idx & 31;
        M[(32 + i) * pm + 32 + j] = t[i * P3 + j];
        M[(32 + i) * pm + j]      = -u[i * P3 + j];
        M[i * pm + 32 + j]        = -u[j * P3 + i];
    }
    __syncthreads();
}

// ---------------- K2: per-class S, S^{-1} (Schur D&C), log2det -------------
__global__ __launch_bounds__(256, 1) void k_sinv() {
    extern __shared__ float sm[];
    float* sS  = sm;                       // 128 * PL
    float* sW  = sS + KDIM * PL;           // 64 * PW
    float* sT  = sW + 64 * PW;
    float* sU  = sT + 64 * PW;
    float* s3a = sU + 64 * PW;             // 32 * P3 x3
    float* s3b = s3a + 32 * P3;
    float* s3c = s3b + 32 * P3;
    __shared__ float s_mu[KDIM];
    __shared__ float s_ld;

    const int c = blockIdx.x, tid = threadIdx.x;

    float rn = 1.0f / (float)g_cnt[c];
    if (tid < KDIM) {
        float m = g_sum[c * KDIM + tid] * rn;
        s_mu[tid] = m;
        g_mu[c * KDIM + tid] = m;
    }
    if (tid == 0) s_ld = 0.0f;
    __syncthreads();

    // build S = G/n - mu mu^T + I  (vectorized; into smem + g_S)
    const float* G = g_G + (size_t)c * MSZ;
    float* Sg = g_S + (size_t)c * MSZ;
    for (int idx = tid; idx < MSZ / 4; idx += 256) {
        int a = idx >> 5, b4 = (idx & 31) << 2;
        float4 s = *(const float4*)&G[a * KDIM + b4];
        float ma = s_mu[a];
        s.x = s.x * rn - ma * s_mu[b4 + 0] + (b4 + 0 == a ? 1.0f : 0.0f);
        s.y = s.y * rn - ma * s_mu[b4 + 1] + (b4 + 1 == a ? 1.0f : 0.0f);
        s.z = s.z * rn - ma * s_mu[b4 + 2] + (b4 + 2 == a ? 1.0f : 0.0f);
        s.w = s.w * rn - ma * s_mu[b4 + 3] + (b4 + 3 == a ? 1.0f : 0.0f);
        *(float4*)&sS[a * PL + b4] = s;
        *(float4*)&Sg[a * KDIM + b4] = s;
    }
    __syncthreads();

    float* Ig = g_inv + (size_t)c * MSZ;

    // ---- S = [[A, Bt],[B, C]] ; two-level Schur inverse ----
    inv64(sS, PL, &s_ld, s3a, s3b, s3c);                     // A -> invA
    sgemm64<false>(sS + 64 * PL, PL, sS, PL, sW, PW, (const float*)0, 0, 0.f, 1.f); // W = B·invA
    __syncthreads();
    sgemm64<false>(sW, PW, sS + 64, PL, sT, PW, sS + 64 * PL + 64, PL, 1.f, -1.f);  // T = C - W·B^T
    __syncthreads();
    inv64(sT, PW, &s_ld, s3a, s3b, s3c);                     // T -> invT
    sgemm64<false>(sT, PW, sW, PW, sU, PW, (const float*)0, 0, 0.f, 1.f);           // U = invT·W
    __syncthreads();
    // write the inverse straight to gmem: TL via GEMM, other blocks elementwise
    sgemm64<true>(sW, PW, sU, PW, Ig, KDIM, sS, PL, 1.f, 1.f);  // TL = invA + W^T·U
    for (int idx = tid; idx < 64 * 64; idx += 256) {
        int i = idx >> 6, j = idx & 63;
        float uv = sU[i * PW + j];
        Ig[(64 + i) * KDIM + 64 + j] = sT[i * PW + j];
        Ig[(64 + i) * KDIM + j]      = -uv;
        Ig[j * KDIM + 64 + i]        = -uv;
    }
    if (tid == 0) g_ld2[c] = s_ld;
}

// ------- K3: pairwise KL, 4x4 class tiles (64 CTAs x 512 thr) --------------
__global__ __launch_bounds__(512) void k_final(float* __restrict__ out) {
    const int i0 = (blockIdx.x & 7) * 4;
    const int j0 = (blockIdx.x >> 3) * 4;
    const int tid = threadIdx.x;
    __shared__ float s_d[16][KDIM];       // per-pair mean diffs (8 KB)
    __shared__ float s_tr[16], s_qd[16];
    __shared__ float s_m2;

    if (tid < 16) { s_tr[tid] = 0.0f; s_qd[tid] = 0.0f; }
    if (tid == 16) s_m2 = 0.0f;
    for (int t = tid; t < 16 * KDIM; t += 512) {
        int p = t >> 7, a = t & 127;
        s_d[p][a] = g_mu[(i0 + (p >> 2)) * KDIM + a] - g_mu[(j0 + (p & 3)) * KDIM + a];
    }
    __syncthreads();

    float tr[16], qd[16];
#pragma unroll
    for (int p = 0; p < 16; p++) { tr[p] = 0.0f; qd[p] = 0.0f; }

    for (int idx = tid; idx < MSZ; idx += 512) {
        const int a = idx >> 7, b = idx & 127;
        float Sv[4], Iv[4];
#pragma unroll
        for (int u = 0; u < 4; u++) Sv[u] = g_S[(size_t)(i0 + u) * MSZ + idx];
#pragma unroll
        for (int u = 0; u < 4; u++) Iv[u] = g_inv[(size_t)(j0 + u) * MSZ + idx];
#pragma unroll
        for (int ui = 0; ui < 4; ui++)
#pragma unroll
            for (int uj = 0; uj < 4; uj++) {
                int p = ui * 4 + uj;
                float w = Iv[uj];
                tr[p] = fmaf(w, Sv[ui], tr[p]);
                qd[p] = fmaf(w * s_d[p][a], s_d[p][b], qd[p]);
            }
    }

    // warp reduce each pair, then shared atomics
#pragma unroll
    for (int p = 0; p < 16; p++) {
#pragma unroll
        for (int o = 16; o; o >>= 1) {
            tr[p] += __shfl_xor_sync(0xffffffffu, tr[p], o);
            qd[p] += __shfl_xor_sync(0xffffffffu, qd[p], o);
        }
    }
    if ((tid & 31) == 0) {
#pragma unroll
        for (int p = 0; p < 16; p++) {
            atomicAdd(&s_tr[p], tr[p]);
            atomicAdd(&s_qd[p], qd[p]);
        }
    }

    // block 0: -sum(mu^2)
    if (blockIdx.x == 0) {
        float m2 = 0.0f;
        for (int t = tid; t < CLS * KDIM; t += 512) { float m = g_mu[t]; m2 += m * m; }
#pragma unroll
        for (int o = 16; o; o >>= 1) m2 += __shfl_xor_sync(0xffffffffu, m2, o);
        if ((tid & 31) == 0) atomicAdd(&s_m2, m2);
    }
    __syncthreads();

    if (tid < 16) {
        int i = i0 + (tid >> 2), j = j0 + (tid & 3);
        int fi = g_first[i], fj = g_first[j], ri = 0, rj = 0;
        for (int c = 0; c < CLS; c++) { int f = g_first[c]; ri += (f < fi); rj += (f < fj); }
        if (ri <= CLS - 2 && rj >= 1) {
            float kl = 0.5f * ((g_ld2[j] - g_ld2[i]) - (float)KDIM + s_qd[tid] + s_tr[tid]);
            atomicAdd(out, kl);
        }
    }
    if (blockIdx.x == 0 && tid == 16) atomicAdd(out, -s_m2);
}

// ---------------- launch ----------------
extern "C" void kernel_launch(void* const* d_in, const int* in_sizes, int n_in,
                              void* d_out, int out_size) {
    const float* feat = (const float*)d_in[0];
    const int*   lab  = (const int*)d_in[1];
    float* out = (float*)d_out;

    const int SINV_SMEM = (KDIM * PL + 3 * 64 * PW + 3 * 32 * P3) * (int)sizeof(float);
    cudaFuncSetAttribute(k_sinv, cudaFuncAttributeMaxDynamicSharedMemorySize, SINV_SMEM);

    k_init<<<(CLS * MSZ + 255) / 256, 256>>>(out);
    k_scatter<<<dim3(RCHUNK, CLS), 256>>>(feat, lab);
    k_sinv<<<CLS, 256, SINV_SMEM>>>();
    k_final<<<64, 512>>>(out);
}

// round 8
// speedup vs baseline: 1.3235x; 1.1318x over previous
#include <cuda_runtime.h>
#include <math.h>

#define BATCH 16384
#define KDIM 128
#define CLS 32
#define PL 132             // sS pitch (%4==0)
#define PW 68              // 64-block pitch (%4==0)
#define P3 36              // 32-block pitch (%4==0)
#define PT 33              // k_tr staging pitch (conflict-free)
#define RCHUNK 8
#define RPC (BATCH / RCHUNK)   // 2048
#define MSZ (KDIM * KDIM)      // 16384

// ---------------- scratch (device globals: allocation-free) ----------------
__device__ float g_sum[CLS * KDIM];
__device__ int   g_cnt[CLS];
__device__ int   g_first[CLS];
__device__ float g_G[CLS * MSZ];
__device__ float g_S[CLS * MSZ];
__device__ float g_inv[CLS * MSZ];
__device__ float g_mu[CLS * KDIM];
__device__ float g_w[CLS * KDIM];      // w_c = inv_c · mu_c
__device__ float g_ld2[CLS];
__device__ float g_TR[CLS * CLS];      // tr(inv_j S_i)
__device__ float g_P[CLS * CLS];       // mu_i^T inv_j mu_i

// ---------------- K0: zero scratch + output ----------------
__global__ void k_init(float* out) {
    int i = blockIdx.x * blockDim.x + threadIdx.x;
    if (i < CLS * MSZ) g_G[i] = 0.0f;
    if (i < CLS * KDIM) g_sum[i] = 0.0f;
    if (i < CLS * CLS) { g_TR[i] = 0.0f; g_P[i] = 0.0f; }
    if (i < CLS) { g_cnt[i] = 0; g_first[i] = BATCH; }
    if (i == 0) out[0] = 0.0f;
}

// ------- K1: per-class Gram (atomic) + fused sums/count/first --------------
__global__ __launch_bounds__(256) void k_scatter(const float* __restrict__ feat,
                                                 const int* __restrict__ lab) {
    const int c = blockIdx.y;
    const int chunk = blockIdx.x;
    const int R0 = chunk * RPC;
    __shared__ int s_idx[RPC];
    __shared__ int s_n, s_min;
    __shared__ __align__(16) float s_x[16][KDIM];
    const int tid = threadIdx.x;
    if (tid == 0) { s_n = 0; s_min = BATCH; }
    __syncthreads();

    for (int r = R0 + tid; r < R0 + RPC; r += 256) {
        if (lab[r] == c) {
            int p = atomicAdd(&s_n, 1);
            s_idx[p] = r;
            atomicMin(&s_min, r);
        }
    }
    __syncthreads();
    const int n = s_n;
    if (n == 0) return;

    float acc[8][8];
#pragma unroll
    for (int u = 0; u < 8; u++)
#pragma unroll
        for (int v = 0; v < 8; v++) acc[u][v] = 0.0f;
    float csum = 0.0f;

    const int ty = tid >> 4, tx = tid & 15;

    for (int t = 0; t < n; t += 16) {
        int m = min(16, n - t);
        for (int i = tid; i < m * 32; i += 256) {
            int rr = i >> 5, q = i & 31;
            ((float4*)s_x[rr])[q] =
                ((const float4*)(feat + (size_t)s_idx[t + rr] * KDIM))[q];
        }
        __syncthreads();
        if (tid < KDIM)
            for (int e = 0; e < m; e++) csum += s_x[e][tid];
        for (int e = 0; e < m; e++) {
            float a[8], b[8];
#pragma unroll
            for (int u = 0; u < 8; u++) { a[u] = s_x[e][ty * 8 + u]; b[u] = s_x[e][tx * 8 + u]; }
#pragma unroll
            for (int u = 0; u < 8; u++)
#pragma unroll
                for (int v = 0; v < 8; v++) acc[u][v] = fmaf(a[u], b[v], acc[u][v]);
        }
        __syncthreads();
    }

    float* G = g_G + (size_t)c * MSZ;
#pragma unroll
    for (int u = 0; u < 8; u++)
#pragma unroll
        for (int v = 0; v < 8; v++)
            atomicAdd(&G[(ty * 8 + u) * KDIM + (tx * 8 + v)], acc[u][v]);

    if (tid < KDIM) atomicAdd(&g_sum[c * KDIM + tid], csum);
    if (tid == 0) { atomicAdd(&g_cnt[c], n); atomicMin(&g_first[c], s_min); }
}

// ---------------- warp Gauss-Jordan inverse of SPD 32x32 (in-place) --------
__device__ __forceinline__ void gj32(float* M, int P, float* ldacc) {
    const int lane = threadIdx.x & 31;
    float y[32];
#pragma unroll
    for (int m = 0; m < 32; m++) y[m] = M[lane * P + m];
    float ld = 0.0f;
#pragma unroll
    for (int j = 0; j < 32; j++) {
        float pj = __shfl_sync(0xffffffffu, y[j], j);
        float r = __fdividef(1.0f, pj);
        float c = y[j];
        if (lane == j) {
            ld = log2f(pj);
#pragma unroll
            for (int m = 0; m < 32; m++) y[m] *= r;
            y[j] = r;
        }
#pragma unroll
        for (int m = 0; m < 32; m++) {
            float rowj = __shfl_sync(0xffffffffu, y[m], j);
            if (lane != j && m != j) y[m] -= c * rowj;
        }
        if (lane != j) y[j] = -c * r;
    }
#pragma unroll
    for (int m = 0; m < 32; m++) M[lane * P + m] = y[m];
#pragma unroll
    for (int o = 16; o; o >>= 1) ld += __shfl_xor_sync(0xffffffffu, ld, o);
    if (lane == 0) *ldacc += ld;
}

// ------ 64-GEMM (256 thr, 4x4 tiles): O = c0s*C0 + sgn*op(P)·Q -------------
template<bool TRA>
__device__ __forceinline__ void sgemm64(const float* __restrict__ P, int pp,
                                        const float* __restrict__ Q, int pq,
                                        float* __restrict__ O, int po,
                                        const float* __restrict__ C0, int pc,
                                        float c0s, float sgn) {
    const int r0 = (threadIdx.x >> 4) * 4;
    const int c0 = (threadIdx.x & 15) * 4;
    float acc[4][4];
#pragma unroll
    for (int u = 0; u < 4; u++)
#pragma unroll
        for (int v = 0; v < 4; v++) acc[u][v] = 0.0f;
#pragma unroll 4
    for (int m = 0; m < 64; m++) {
        float4 b = *(const float4*)&Q[m * pq + c0];
        float a[4];
        if (TRA) {
            float4 t = *(const float4*)&P[m * pp + r0];
            a[0] = t.x; a[1] = t.y; a[2] = t.z; a[3] = t.w;
        } else {
#pragma unroll
            for (int u = 0; u < 4; u++) a[u] = P[(r0 + u) * pp + m];
        }
#pragma unroll
        for (int u = 0; u < 4; u++) {
            acc[u][0] = fmaf(a[u], b.x, acc[u][0]);
            acc[u][1] = fmaf(a[u], b.y, acc[u][1]);
            acc[u][2] = fmaf(a[u], b.z, acc[u][2]);
            acc[u][3] = fmaf(a[u], b.w, acc[u][3]);
        }
    }
#pragma unroll
    for (int u = 0; u < 4; u++) {
        float4 o = make_float4(sgn * acc[u][0], sgn * acc[u][1],
                               sgn * acc[u][2], sgn * acc[u][3]);
        if (C0) {
            float4 cc = *(const float4*)&C0[(r0 + u) * pc + c0];
            o.x += c0s * cc.x; o.y += c0s * cc.y;
            o.z += c0s * cc.z; o.w += c0s * cc.w;
        }
        *(float4*)&O[(r0 + u) * po + c0] = o;
    }
}

// ------ 32-GEMM (256 thr, 2x2 tiles) ----------------------------------------
template<bool TRA>
__device__ __forceinline__ void sgemm32(const float* __restrict__ P, int pp,
                                        const float* __restrict__ Q, int pq,
                                        float* __restrict__ O, int po,
                                        const float* __restrict__ C0, int pc,
                                        float c0s, float sgn) {
    const int r0 = (threadIdx.x >> 4) * 2;
    const int c0 = (threadIdx.x & 15) * 2;
    float acc[2][2] = {{0.f, 0.f}, {0.f, 0.f}};
#pragma unroll 8
    for (int m = 0; m < 32; m++) {
        float2 b = *(const float2*)&Q[m * pq + c0];
        float a0 = TRA ? P[m * pp + r0]     : P[r0 * pp + m];
        float a1 = TRA ? P[m * pp + r0 + 1] : P[(r0 + 1) * pp + m];
        acc[0][0] = fmaf(a0, b.x, acc[0][0]); acc[0][1] = fmaf(a0, b.y, acc[0][1]);
        acc[1][0] = fmaf(a1, b.x, acc[1][0]); acc[1][1] = fmaf(a1, b.y, acc[1][1]);
    }
#pragma unroll
    for (int u = 0; u < 2; u++) {
        float2 o = make_float2(sgn * acc[u][0], sgn * acc[u][1]);
        if (C0) {
            float2 cc = *(const float2*)&C0[(r0 + u) * pc + c0];
            o.x += c0s * cc.x; o.y += c0s * cc.y;
        }
        *(float2*)&O[(r0 + u) * po + c0] = o;
    }
}

// ---------------- 64x64 SPD inverse via one-level Schur (in place) ---------
__device__ void inv64(float* M, int pm, float* ldacc,
                      float* w, float* t, float* u) {
    if (threadIdx.x < 32) gj32(M, pm, ldacc);               // a -> inva
    __syncthreads();
    sgemm32<false>(M + 32 * pm, pm, M, pm, w, P3, (const float*)0, 0, 0.f, 1.f);
    __syncthreads();
    sgemm32<false>(w, P3, M + 32, pm, t, P3, M + 32 * pm + 32, pm, 1.f, -1.f);
    __syncthreads();
    if (threadIdx.x < 32) gj32(t, P3, ldacc);               // t -> invt
    __syncthreads();
    sgemm32<false>(t, P3, w, P3, u, P3, (const float*)0, 0, 0.f, 1.f);
    __syncthreads();
    sgemm32<true>(w, P3, u, P3, M, pm, M, pm, 1.f, 1.f);    // TL = inva + w^T u
    for (int idx = threadIdx.x; idx < 1024; idx += 256) {
        int i = idx >> 5, j = idx & 31;
        M[(32 + i) * pm + 32 + j] = t[i * P3 + j];
        M[(32 + i) * pm + j]      = -u[i * P3 + j];
        M[i * pm + 32 + j]        = -u[j * P3 + i];
    }
    __syncthreads();
}

// ---------------- K2: per-class S, S^{-1}, log2det, w = inv·mu -------------
__global__ __launch_bounds__(256, 1) void k_sinv() {
    extern __shared__ float sm[];
    float* sS  = sm;                       // 128 * PL
    float* sW  = sS + KDIM * PL;           // 64 * PW
    float* sT  = sW + 64 * PW;
    float* sU  = sT + 64 * PW;
    float* s3a = sU + 64 * PW;             // 32 * P3 x3
    float* s3b = s3a + 32 * P3;
    float* s3c = s3b + 32 * P3;
    __shared__ float s_mu[KDIM];
    __shared__ float s_ld;

    const int c = blockIdx.x, tid = threadIdx.x;

    float rn = 1.0f / (float)g_cnt[c];
    if (tid < KDIM) {
        float m = g_sum[c * KDIM + tid] * rn;
        s_mu[tid] = m;
        g_mu[c * KDIM + tid] = m;
    }
    if (tid == 0) s_ld = 0.0f;
    __syncthreads();

    // build S = G/n - mu mu^T + I  (vectorized; into smem + g_S)
    const float* G = g_G + (size_t)c * MSZ;
    float* Sg = g_S + (size_t)c * MSZ;
    for (int idx = tid; idx < MSZ / 4; idx += 256) {
        int a = idx >> 5, b4 = (idx & 31) << 2;
        float4 s = *(const float4*)&G[a * KDIM + b4];
        float ma = s_mu[a];
        s.x = s.x * rn - ma * s_mu[b4 + 0] + (b4 + 0 == a ? 1.0f : 0.0f);
        s.y = s.y * rn - ma * s_mu[b4 + 1] + (b4 + 1 == a ? 1.0f : 0.0f);
        s.z = s.z * rn - ma * s_mu[b4 + 2] + (b4 + 2 == a ? 1.0f : 0.0f);
        s.w = s.w * rn - ma * s_mu[b4 + 3] + (b4 + 3 == a ? 1.0f : 0.0f);
        *(float4*)&sS[a * PL + b4] = s;
        *(float4*)&Sg[a * KDIM + b4] = s;
    }
    __syncthreads();

    float* Ig = g_inv + (size_t)c * MSZ;

    // ---- S = [[A, Bt],[B, C]] ; two-level Schur inverse ----
    inv64(sS, PL, &s_ld, s3a, s3b, s3c);                     // A -> invA
    sgemm64<false>(sS + 64 * PL, PL, sS, PL, sW, PW, (const float*)0, 0, 0.f, 1.f); // W = B·invA
    __syncthreads();
    sgemm64<false>(sW, PW, sS + 64, PL, sT, PW, sS + 64 * PL + 64, PL, 1.f, -1.f);  // T = C - W·B^T
    __syncthreads();
    inv64(sT, PW, &s_ld, s3a, s3b, s3c);                     // T -> invT
    sgemm64<false>(sT, PW, sW, PW, sU, PW, (const float*)0, 0, 0.f, 1.f);           // U = invT·W
    __syncthreads();
    // write the inverse straight to gmem: TL via GEMM, other blocks elementwise
    sgemm64<true>(sW, PW, sU, PW, Ig, KDIM, sS, PL, 1.f, 1.f);  // TL = invA + W^T·U
    for (int idx = tid; idx < 64 * 64; idx += 256) {
        int i = idx >> 6, j = idx & 63;
        float uv = sU[i * PW + j];
        Ig[(64 + i) * KDIM + 64 + j] = sT[i * PW + j];
        Ig[(64 + i) * KDIM + j]      = -uv;
        Ig[j * KDIM + 64 + i]        = -uv;
    }
    __syncthreads();

    // w = inv · mu  (rows are L1-hot; float4 dots)
    if (tid < KDIM) {
        const float4* row = (const float4*)&Ig[tid * KDIM];
        float s = 0.0f;
#pragma unroll
        for (int q = 0; q < 32; q++) {
            float4 v = row[q];
            s += v.x * s_mu[q * 4] + v.y * s_mu[q * 4 + 1]
               + v.z * s_mu[q * 4 + 2] + v.w * s_mu[q * 4 + 3];
        }
        g_w[c * KDIM + tid] = s;
    }
    if (tid == 0) g_ld2[c] = s_ld;
}

// ------- K3: TR[i][j] = <S_i, inv_j>, Praw[i][j] accumulation --------------
// grid 128: one CTA per matrix row a0; per-chunk partials via global atomics.
__global__ __launch_bounds__(256) void k_tr() {
    extern __shared__ float sm[];
    float* sS  = sm;                 // [k][cl] pitch PT
    float* sI  = sS + 128 * PT;
    float* sMU = sI + 128 * PT;
    __shared__ float sMUa[32];
    const int a0 = blockIdx.x;
    const int tid = threadIdx.x;

    for (int idx = tid; idx < 1024; idx += 256) {
        int cl = idx >> 5, q = idx & 31;
        int k = q << 2;
        float4 vs = *(const float4*)&g_S[(size_t)cl * MSZ + a0 * KDIM + k];
        float4 vi = *(const float4*)&g_inv[(size_t)cl * MSZ + a0 * KDIM + k];
        float4 vm = *(const float4*)&g_mu[cl * KDIM + k];
        sS[k * PT + cl] = vs.x; sS[(k+1) * PT + cl] = vs.y;
        sS[(k+2) * PT + cl] = vs.z; sS[(k+3) * PT + cl] = vs.w;
        sI[k * PT + cl] = vi.x; sI[(k+1) * PT + cl] = vi.y;
        sI[(k+2) * PT + cl] = vi.z; sI[(k+3) * PT + cl] = vi.w;
        sMU[k * PT + cl] = vm.x; sMU[(k+1) * PT + cl] = vm.y;
        sMU[(k+2) * PT + cl] = vm.z; sMU[(k+3) * PT + cl] = vm.w;
    }
    if (tid < 32) sMUa[tid] = g_mu[tid * KDIM + a0];
    __syncthreads();

    const int i0 = (tid >> 4) * 2, j0 = (tid & 15) * 2;
    float t00 = 0, t01 = 0, t10 = 0, t11 = 0;
    float p00 = 0, p01 = 0, p10 = 0, p11 = 0;
#pragma unroll 4
    for (int k = 0; k < 128; k++) {
        float b0 = sI[k * PT + j0], b1 = sI[k * PT + j0 + 1];
        float s0 = sS[k * PT + i0], s1 = sS[k * PT + i0 + 1];
        float m0 = sMU[k * PT + i0], m1 = sMU[k * PT + i0 + 1];
        t00 = fmaf(s0, b0, t00); t01 = fmaf(s0, b1, t01);
        t10 = fmaf(s1, b0, t10); t11 = fmaf(s1, b1, t11);
        p00 = fmaf(m0, b0, p00); p01 = fmaf(m0, b1, p01);
        p10 = fmaf(m1, b0, p10); p11 = fmaf(m1, b1, p11);
    }
    float mA0 = sMUa[i0], mA1 = sMUa[i0 + 1];
    atomicAdd(&g_TR[i0 * 32 + j0],     t00);
    atomicAdd(&g_TR[i0 * 32 + j0 + 1], t01);
    atomicAdd(&g_TR[(i0 + 1) * 32 + j0],     t10);
    atomicAdd(&g_TR[(i0 + 1) * 32 + j0 + 1], t11);
    atomicAdd(&g_P[i0 * 32 + j0],     mA0 * p00);
    atomicAdd(&g_P[i0 * 32 + j0 + 1], mA0 * p01);
    atomicAdd(&g_P[(i0 + 1) * 32 + j0],     mA1 * p10);
    atomicAdd(&g_P[(i0 + 1) * 32 + j0 + 1], mA1 * p11);
}

// ------- K4: combine — R dots, mask, KL sum, -|mu|^2 ------------------------
__global__ __launch_bounds__(256) void k_comb(float* __restrict__ out) {
    __shared__ float s_mu[32 * 128];
    __shared__ float s_w[32 * 129];
    __shared__ int   s_rank[32];
    __shared__ float s_part[8];
    const int tid = threadIdx.x;

    for (int idx = tid; idx < 1024; idx += 256) {
        int cl = idx >> 5, q = idx & 31;
        int k = q << 2;
        *(float4*)&s_mu[cl * 128 + k] = *(const float4*)&g_mu[cl * KDIM + k];
        float4 w = *(const float4*)&g_w[cl * KDIM + k];
        s_w[cl * 129 + k] = w.x; s_w[cl * 129 + k + 1] = w.y;
        s_w[cl * 129 + k + 2] = w.z; s_w[cl * 129 + k + 3] = w.w;
    }
    if (tid < 32) {
        int f = g_first[tid], r = 0;
        for (int c = 0; c < 32; c++) r += (g_first[c] < f);
        s_rank[tid] = r;
    }
    __syncthreads();

    const int pi = blockIdx.x * 256 + tid;     // pair 0..1023 (grid 4)
    const int i = pi >> 5, j = pi & 31;
    float acc = 0.0f;
    if (s_rank[i] <= CLS - 2 && s_rank[j] >= 1) {
        const float* mi = &s_mu[i * 128];
        const float* wj = &s_w[j * 129];
        float r = 0.0f;
#pragma unroll 8
        for (int k = 0; k < 128; k++) r = fmaf(mi[k], wj[k], r);
        float qd = g_P[i * 32 + j] - 2.0f * r + g_P[j * 32 + j];
        acc = 0.5f * ((g_ld2[j] - g_ld2[i]) - (float)KDIM + qd + g_TR[i * 32 + j]);
    }
    if (blockIdx.x == 0) {
        float m2 = 0.0f;
        for (int t = tid; t < 4096; t += 256) { float m = s_mu[t]; m2 += m * m; }
        acc -= m2;
    }
#pragma unroll
    for (int o = 16; o; o >>= 1) acc += __shfl_xor_sync(0xffffffffu, acc, o);
    if ((tid & 31) == 0) s_part[tid >> 5] = acc;
    __syncthreads();
    if (tid == 0) {
        float s = 0.0f;
#pragma unroll
        for (int wp = 0; wp < 8; wp++) s += s_part[wp];
        atomicAdd(out, s);
    }
}

// ---------------- launch ----------------
extern "C" void kernel_launch(void* const* d_in, const int* in_sizes, int n_in,
                              void* d_out, int out_size) {
    const float* feat = (const float*)d_in[0];
    const int*   lab  = (const int*)d_in[1];
    float* out = (float*)d_out;

    const int SINV_SMEM = (KDIM * PL + 3 * 64 * PW + 3 * 32 * P3) * (int)sizeof(float);
    const int TR_SMEM   = 3 * 128 * PT * (int)sizeof(float);   // 50688
    cudaFuncSetAttribute(k_sinv, cudaFuncAttributeMaxDynamicSharedMemorySize, SINV_SMEM);
    cudaFuncSetAttribute(k_tr,   cudaFuncAttributeMaxDynamicSharedMemorySize, TR_SMEM);

    k_init<<<(CLS * MSZ + 255) / 256, 256>>>(out);
    k_scatter<<<dim3(RCHUNK, CLS), 256>>>(feat, lab);
    k_sinv<<<CLS, 256, SINV_SMEM>>>();
    k_tr<<<KDIM, 256, TR_SMEM>>>();
    k_comb<<<4, 256>>>(out);
}

// round 9
// speedup vs baseline: 1.3783x; 1.0414x over previous
#include <cuda_runtime.h>
#include <math.h>

#define BATCH 16384
#define KDIM 128
#define CLS 32
#define PL 132             // sS pitch (%4==0)
#define PW 68              // 64-block pitch (%4==0)
#define P3 36              // 32-block pitch (%4==0)
#define PT 33              // k_tr staging pitch (conflict-free)
#define RCHUNK 8
#define RPC (BATCH / RCHUNK)   // 2048
#define MSZ (KDIM * KDIM)      // 16384

// ---------------- scratch (device globals: allocation-free) ----------------
__device__ float g_sum[CLS * KDIM];
__device__ int   g_cnt[CLS];
__device__ int   g_first[CLS];
__device__ float g_G[CLS * MSZ];       // lower triangle valid
__device__ float g_S[CLS * MSZ];
__device__ float g_inv[CLS * MSZ];
__device__ float g_mu[CLS * KDIM];
__device__ float g_w[CLS * KDIM];      // w_c = inv_c · mu_c
__device__ float g_ld2[CLS];
__device__ float g_TR[CLS * CLS];      // tr(inv_j S_i)
__device__ float g_P[CLS * CLS];       // mu_i^T inv_j mu_i

// ---------------- K0a: zero Gram scratch ----------------
__global__ void k_init0() {
    int i = blockIdx.x * blockDim.x + threadIdx.x;
    if (i < CLS * MSZ) g_G[i] = 0.0f;
}

// ---------------- K0b: zero small scratch + output ----------------
__global__ void k_init1(float* out) {
    int i = blockIdx.x * blockDim.x + threadIdx.x;
    if (i < CLS * KDIM) g_sum[i] = 0.0f;
    if (i < CLS * CLS) { g_TR[i] = 0.0f; g_P[i] = 0.0f; }
    if (i < CLS) { g_cnt[i] = 0; g_first[i] = BATCH; }
    if (i == 0) out[0] = 0.0f;
}

// ------- K1: per-class Gram (atomic, lower tri) + fused sums/count/first ---
__global__ __launch_bounds__(256) void k_scatter(const float* __restrict__ feat,
                                                 const int* __restrict__ lab) {
    const int c = blockIdx.y;
    const int chunk = blockIdx.x;
    const int R0 = chunk * RPC;
    __shared__ int s_idx[RPC];
    __shared__ int s_n, s_min;
    __shared__ __align__(16) float s_x[16][KDIM];
    const int tid = threadIdx.x;
    if (tid == 0) { s_n = 0; s_min = BATCH; }
    __syncthreads();

    for (int r = R0 + tid; r < R0 + RPC; r += 256) {
        if (lab[r] == c) {
            int p = atomicAdd(&s_n, 1);
            s_idx[p] = r;
            atomicMin(&s_min, r);
        }
    }
    __syncthreads();
    const int n = s_n;
    if (n == 0) return;

    float acc[8][8];
#pragma unroll
    for (int u = 0; u < 8; u++)
#pragma unroll
        for (int v = 0; v < 8; v++) acc[u][v] = 0.0f;
    float csum = 0.0f;

    const int ty = tid >> 4, tx = tid & 15;

    for (int t = 0; t < n; t += 16) {
        int m = min(16, n - t);
        for (int i = tid; i < m * 32; i += 256) {
            int rr = i >> 5, q = i & 31;
            ((float4*)s_x[rr])[q] =
                ((const float4*)(feat + (size_t)s_idx[t + rr] * KDIM))[q];
        }
        __syncthreads();
        if (tid < KDIM)
            for (int e = 0; e < m; e++) csum += s_x[e][tid];
        for (int e = 0; e < m; e++) {
            float a[8], b[8];
#pragma unroll
            for (int u = 0; u < 8; u++) { a[u] = s_x[e][ty * 8 + u]; b[u] = s_x[e][tx * 8 + u]; }
#pragma unroll
            for (int u = 0; u < 8; u++)
#pragma unroll
                for (int v = 0; v < 8; v++) acc[u][v] = fmaf(a[u], b[v], acc[u][v]);
        }
        __syncthreads();
    }

    // lower triangle only (col <= row) — halves global atomic traffic
    float* G = g_G + (size_t)c * MSZ;
    if (tx <= ty) {
#pragma unroll
        for (int u = 0; u < 8; u++)
#pragma unroll
            for (int v = 0; v < 8; v++) {
                int row = ty * 8 + u, col = tx * 8 + v;
                if (col <= row)
                    atomicAdd(&G[row * KDIM + col], acc[u][v]);
            }
    }

    if (tid < KDIM) atomicAdd(&g_sum[c * KDIM + tid], csum);
    if (tid == 0) { atomicAdd(&g_cnt[c], n); atomicMin(&g_first[c], s_min); }
}

// ---------------- warp Gauss-Jordan inverse of SPD 32x32 (in-place) --------
__device__ __forceinline__ void gj32(float* M, int P, float* ldacc) {
    const int lane = threadIdx.x & 31;
    float y[32];
#pragma unroll
    for (int m = 0; m < 32; m++) y[m] = M[lane * P + m];
    float ld = 0.0f;
#pragma unroll
    for (int j = 0; j < 32; j++) {
        float pj = __shfl_sync(0xffffffffu, y[j], j);
        float r = __fdividef(1.0f, pj);
        float c = y[j];
        if (lane == j) {
            ld = log2f(pj);
#pragma unroll
            for (int m = 0; m < 32; m++) y[m] *= r;
            y[j] = r;
        }
#pragma unroll
        for (int m = 0; m < 32; m++) {
            float rowj = __shfl_sync(0xffffffffu, y[m], j);
            if (lane != j && m != j) y[m] -= c * rowj;
        }
        if (lane != j) y[j] = -c * r;
    }
#pragma unroll
    for (int m = 0; m < 32; m++) M[lane * P + m] = y[m];
#pragma unroll
    for (int o = 16; o; o >>= 1) ld += __shfl_xor_sync(0xffffffffu, ld, o);
    if (lane == 0) *ldacc += ld;
}

// ------ 64-GEMM (256 thr, 4x4 tiles): O = c0s*C0 + sgn*op(P)·Q -------------
template<bool TRA>
__device__ __forceinline__ void sgemm64(const float* __restrict__ P, int pp,
                                        const float* __restrict__ Q, int pq,
                                        float* __restrict__ O, int po,
                                        const float* __restrict__ C0, int pc,
                                        float c0s, float sgn) {
    const int r0 = (threadIdx.x >> 4) * 4;
    const int c0 = (threadIdx.x & 15) * 4;
    float acc[4][4];
#pragma unroll
    for (int u = 0; u < 4; u++)
#pragma unroll
        for (int v = 0; v < 4; v++) acc[u][v] = 0.0f;
#pragma unroll 4
    for (int m = 0; m < 64; m++) {
        float4 b = *(const float4*)&Q[m * pq + c0];
        float a[4];
        if (TRA) {
            float4 t = *(const float4*)&P[m * pp + r0];
            a[0] = t.x; a[1] = t.y; a[2] = t.z; a[3] = t.w;
        } else {
#pragma unroll
            for (int u = 0; u < 4; u++) a[u] = P[(r0 + u) * pp + m];
        }
#pragma unroll
        for (int u = 0; u < 4; u++) {
            acc[u][0] = fmaf(a[u], b.x, acc[u][0]);
            acc[u][1] = fmaf(a[u], b.y, acc[u][1]);
            acc[u][2] = fmaf(a[u], b.z, acc[u][2]);
            acc[u][3] = fmaf(a[u], b.w, acc[u][3]);
        }
    }
#pragma unroll
    for (int u = 0; u < 4; u++) {
        float4 o = make_float4(sgn * acc[u][0], sgn * acc[u][1],
                               sgn * acc[u][2], sgn * acc[u][3]);
        if (C0) {
            float4 cc = *(const float4*)&C0[(r0 + u) * pc + c0];
            o.x += c0s * cc.x; o.y += c0s * cc.y;
            o.z += c0s * cc.z; o.w += c0s * cc.w;
        }
        *(float4*)&O[(r0 + u) * po + c0] = o;
    }
}

// ------ 32-GEMM (256 thr, 2x2 tiles) ----------------------------------------
template<bool TRA>
__device__ __forceinline__ void sgemm32(const float* __restrict__ P, int pp,
                                        const float* __restrict__ Q, int pq,
                                        float* __restrict__ O, int po,
                                        const float* __restrict__ C0, int pc,
                                        float c0s, float sgn) {
    const int r0 = (threadIdx.x >> 4) * 2;
    const int c0 = (threadIdx.x & 15) * 2;
    float acc[2][2] = {{0.f, 0.f}, {0.f, 0.f}};
#pragma unroll 8
    for (int m = 0; m < 32; m++) {
        float2 b = *(const float2*)&Q[m * pq + c0];
        float a0 = TRA ? P[m * pp + r0]     : P[r0 * pp + m];
        float a1 = TRA ? P[m * pp + r0 + 1] : P[(r0 + 1) * pp + m];
        acc[0][0] = fmaf(a0, b.x, acc[0][0]); acc[0][1] = fmaf(a0, b.y, acc[0][1]);
        acc[1][0] = fmaf(a1, b.x, acc[1][0]); acc[1][1] = fmaf(a1, b.y, acc[1][1]);
    }
#pragma unroll
    for (int u = 0; u < 2; u++) {
        float2 o = make_float2(sgn * acc[u][0], sgn * acc[u][1]);
        if (C0) {
            float2 cc = *(const float2*)&C0[(r0 + u) * pc + c0];
            o.x += c0s * cc.x; o.y += c0s * cc.y;
        }
        *(float2*)&O[(r0 + u) * po + c0] = o;
    }
}

// ---------------- 64x64 SPD inverse via one-level Schur (in place) ---------
__device__ void inv64(float* M, int pm, float* ldacc,
                      float* w, float* t, float* u) {
    if (threadIdx.x < 32) gj32(M, pm, ldacc);               // a -> inva
    __syncthreads();
    sgemm32<false>(M + 32 * pm, pm, M, pm, w, P3, (const float*)0, 0, 0.f, 1.f);
    __syncthreads();
    sgemm32<false>(w, P3, M + 32, pm, t, P3, M + 32 * pm + 32, pm, 1.f, -1.f);
    __syncthreads();
    if (threadIdx.x < 32) gj32(t, P3, ldacc);               // t -> invt
    __syncthreads();
    sgemm32<false>(t, P3, w, P3, u, P3, (const float*)0, 0, 0.f, 1.f);
    __syncthreads();
    sgemm32<true>(w, P3, u, P3, M, pm, M, pm, 1.f, 1.f);    // TL = inva + w^T u
    for (int idx = threadIdx.x; idx < 1024; idx += 256) {
        int i = idx >> 5, j = idx & 31;
        M[(32 + i) * pm + 32 + j] = t[i * P3 + j];
        M[(32 + i) * pm + j]      = -u[i * P3 + j];
        M[i * pm + 32 + j]        = -u[j * P3 + i];
    }
    __syncthreads();
}

// ---------------- K2: per-class S, S^{-1}, log2det, w = inv·mu -------------
__global__ __launch_bounds__(256, 1) void k_sinv() {
    extern __shared__ float sm[];
    float* sS  = sm;                       // 128 * PL
    float* sW  = sS + KDIM * PL;           // 64 * PW
    float* sT  = sW + 64 * PW;
    float* sU  = sT + 64 * PW;
    float* s3a = sU + 64 * PW;             // 32 * P3 x3
    float* s3b = s3a + 32 * P3;
    float* s3c = s3b + 32 * P3;
    __shared__ float s_mu[KDIM];
    __shared__ float s_ld;

    const int c = blockIdx.x, tid = threadIdx.x;

    float rn = 1.0f / (float)g_cnt[c];
    if (tid < KDIM) {
        float m = g_sum[c * KDIM + tid] * rn;
        s_mu[tid] = m;
        g_mu[c * KDIM + tid] = m;
    }
    if (tid == 0) s_ld = 0.0f;
    __syncthreads();

    // build S = G/n - mu mu^T + I  (G lower triangle valid; mirror reads)
    const float* G = g_G + (size_t)c * MSZ;
    float* Sg = g_S + (size_t)c * MSZ;
#pragma unroll 8
    for (int idx = tid; idx < MSZ; idx += 256) {
        int a = idx >> 7, b = idx & 127;
        float g = (b <= a) ? G[a * KDIM + b] : G[b * KDIM + a];
        float s = g * rn - s_mu[a] * s_mu[b] + (a == b ? 1.0f : 0.0f);
        sS[a * PL + b] = s;
        Sg[idx] = s;
    }
    __syncthreads();

    float* Ig = g_inv + (size_t)c * MSZ;

    // ---- S = [[A, Bt],[B, C]] ; two-level Schur inverse ----
    inv64(sS, PL, &s_ld, s3a, s3b, s3c);                     // A -> invA
    sgemm64<false>(sS + 64 * PL, PL, sS, PL, sW, PW, (const float*)0, 0, 0.f, 1.f); // W = B·invA
    __syncthreads();
    sgemm64<false>(sW, PW, sS + 64, PL, sT, PW, sS + 64 * PL + 64, PL, 1.f, -1.f);  // T = C - W·B^T
    __syncthreads();
    inv64(sT, PW, &s_ld, s3a, s3b, s3c);                     // T -> invT
    sgemm64<false>(sT, PW, sW, PW, sU, PW, (const float*)0, 0, 0.f, 1.f);           // U = invT·W
    __syncthreads();
    // write the inverse straight to gmem: TL via GEMM, other blocks elementwise
    sgemm64<true>(sW, PW, sU, PW, Ig, KDIM, sS, PL, 1.f, 1.f);  // TL = invA + W^T·U
    for (int idx = tid; idx < 64 * 64; idx += 256) {
        int i = idx >> 6, j = idx & 63;
        float uv = sU[i * PW + j];
        Ig[(64 + i) * KDIM + 64 + j] = sT[i * PW + j];
        Ig[(64 + i) * KDIM + j]      = -uv;
        Ig[j * KDIM + 64 + i]        = -uv;
    }
    __syncthreads();

    // w = inv · mu  (rows are L1-hot; float4 dots)
    if (tid < KDIM) {
        const float4* row = (const float4*)&Ig[tid * KDIM];
        float s = 0.0f;
#pragma unroll
        for (int q = 0; q < 32; q++) {
            float4 v = row[q];
            s += v.x * s_mu[q * 4] + v.y * s_mu[q * 4 + 1]
               + v.z * s_mu[q * 4 + 2] + v.w * s_mu[q * 4 + 3];
        }
        g_w[c * KDIM + tid] = s;
    }
    if (tid == 0) g_ld2[c] = s_ld;
}

// ------- K3: TR[i][j] = <S_i, inv_j>, Praw[i][j] accumulation --------------
__global__ __launch_bounds__(256) void k_tr() {
    extern __shared__ float sm[];
    float* sS  = sm;                 // [k][cl] pitch PT
    float* sI  = sS + 128 * PT;
    float* sMU = sI + 128 * PT;
    __shared__ float sMUa[32];
    const int a0 = blockIdx.x;
    const int tid = threadIdx.x;

    for (int idx = tid; idx < 1024; idx += 256) {
        int cl = idx >> 5, q = idx & 31;
        int k = q << 2;
        float4 vs = *(const float4*)&g_S[(size_t)cl * MSZ + a0 * KDIM + k];
        float4 vi = *(const float4*)&g_inv[(size_t)cl * MSZ + a0 * KDIM + k];
        float4 vm = *(const float4*)&g_mu[cl * KDIM + k];
        sS[k * PT + cl] = vs.x; sS[(k+1) * PT + cl] = vs.y;
        sS[(k+2) * PT + cl] = vs.z; sS[(k+3) * PT + cl] = vs.w;
        sI[k * PT + cl] = vi.x; sI[(k+1) * PT + cl] = vi.y;
        sI[(k+2) * PT + cl] = vi.z; sI[(k+3) * PT + cl] = vi.w;
        sMU[k * PT + cl] = vm.x; sMU[(k+1) * PT + cl] = vm.y;
        sMU[(k+2) * PT + cl] = vm.z; sMU[(k+3) * PT + cl] = vm.w;
    }
    if (tid < 32) sMUa[tid] = g_mu[tid * KDIM + a0];
    __syncthreads();

    const int i0 = (tid >> 4) * 2, j0 = (tid & 15) * 2;
    float t00 = 0, t01 = 0, t10 = 0, t11 = 0;
    float p00 = 0, p01 = 0, p10 = 0, p11 = 0;
#pragma unroll 4
    for (int k = 0; k < 128; k++) {
        float b0 = sI[k * PT + j0], b1 = sI[k * PT + j0 + 1];
        float s0 = sS[k * PT + i0], s1 = sS[k * PT + i0 + 1];
        float m0 = sMU[k * PT + i0], m1 = sMU[k * PT + i0 + 1];
        t00 = fmaf(s0, b0, t00); t01 = fmaf(s0, b1, t01);
        t10 = fmaf(s1, b0, t10); t11 = fmaf(s1, b1, t11);
        p00 = fmaf(m0, b0, p00); p01 = fmaf(m0, b1, p01);
        p10 = fmaf(m1, b0, p10); p11 = fmaf(m1, b1, p11);
    }
    float mA0 = sMUa[i0], mA1 = sMUa[i0 + 1];
    atomicAdd(&g_TR[i0 * 32 + j0],     t00);
    atomicAdd(&g_TR[i0 * 32 + j0 + 1], t01);
    atomicAdd(&g_TR[(i0 + 1) * 32 + j0],     t10);
    atomicAdd(&g_TR[(i0 + 1) * 32 + j0 + 1], t11);
    atomicAdd(&g_P[i0 * 32 + j0],     mA0 * p00);
    atomicAdd(&g_P[i0 * 32 + j0 + 1], mA0 * p01);
    atomicAdd(&g_P[(i0 + 1) * 32 + j0],     mA1 * p10);
    atomicAdd(&g_P[(i0 + 1) * 32 + j0 + 1], mA1 * p11);
}

// ------- K4: combine — R dots, mask, KL sum, -|mu|^2 ------------------------
__global__ __launch_bounds__(256) void k_comb(float* __restrict__ out) {
    __shared__ float s_mu[32 * 128];
    __shared__ float s_w[32 * 129];
    __shared__ int   s_rank[32];
    __shared__ float s_part[8];
    const int tid = threadIdx.x;

    for (int idx = tid; idx < 1024; idx += 256) {
        int cl = idx >> 5, q = idx & 31;
        int k = q << 2;
        *(float4*)&s_mu[cl * 128 + k] = *(const float4*)&g_mu[cl * KDIM + k];
        float4 w = *(const float4*)&g_w[cl * KDIM + k];
        s_w[cl * 129 + k] = w.x; s_w[cl * 129 + k + 1] = w.y;
        s_w[cl * 129 + k + 2] = w.z; s_w[cl * 129 + k + 3] = w.w;
    }
    if (tid < 32) {
        int f = g_first[tid], r = 0;
        for (int c = 0; c < 32; c++) r += (g_first[c] < f);
        s_rank[tid] = r;
    }
    __syncthreads();

    const int pi = blockIdx.x * 256 + tid;     // pair 0..1023 (grid 4)
    const int i = pi >> 5, j = pi & 31;
    float acc = 0.0f;
    if (s_rank[i] <= CLS - 2 && s_rank[j] >= 1) {
        const float* mi = &s_mu[i * 128];
        const float* wj = &s_w[j * 129];
        float r = 0.0f;
#pragma unroll 8
        for (int k = 0; k < 128; k++) r = fmaf(mi[k], wj[k], r);
        float qd = g_P[i * 32 + j] - 2.0f * r + g_P[j * 32 + j];
        acc = 0.5f * ((g_ld2[j] - g_ld2[i]) - (float)KDIM + qd + g_TR[i * 32 + j]);
    }
    if (blockIdx.x == 0) {
        float m2 = 0.0f;
        for (int t = tid; t < 4096; t += 256) { float m = s_mu[t]; m2 += m * m; }
        acc -= m2;
    }
#pragma unroll
    for (int o = 16; o; o >>= 1) acc += __shfl_xor_sync(0xffffffffu, acc, o);
    if ((tid & 31) == 0) s_part[tid >> 5] = acc;
    __syncthreads();
    if (tid == 0) {
        float s = 0.0f;
#pragma unroll
        for (int wp = 0; wp < 8; wp++) s += s_part[wp];
        atomicAdd(out, s);
    }
}

// ---------------- launch ----------------
extern "C" void kernel_launch(void* const* d_in, const int* in_sizes, int n_in,
                              void* d_out, int out_size) {
    const float* feat = (const float*)d_in[0];
    const int*   lab  = (const int*)d_in[1];
    float* out = (float*)d_out;

    const int SINV_SMEM = (KDIM * PL + 3 * 64 * PW + 3 * 32 * P3) * (int)sizeof(float);
    const int TR_SMEM   = 3 * 128 * PT * (int)sizeof(float);   // 50688
    cudaFuncSetAttribute(k_sinv, cudaFuncAttributeMaxDynamicSharedMemorySize, SINV_SMEM);
    cudaFuncSetAttribute(k_tr,   cudaFuncAttributeMaxDynamicSharedMemorySize, TR_SMEM);

    k_init0<<<(CLS * MSZ + 255) / 256, 256>>>();
    k_init1<<<16, 256>>>(out);
    k_scatter<<<dim3(RCHUNK, CLS), 256>>>(feat, lab);
    k_sinv<<<CLS, 256, SINV_SMEM>>>();          // capture position 4
    k_tr<<<KDIM, 256, TR_SMEM>>>();
    k_comb<<<4, 256>>>(out);
}